// round 3
// baseline (speedup 1.0000x reference)
#include <cuda_runtime.h>
#include <math.h>

#define SEQ 2048
#define BATCH 16
#define HID 1024

// Scratch (allocation-free rule: __device__ globals)
__device__ float    g_energy[BATCH * HID];   // [B, H]
__device__ float    g_scores[SEQ * BATCH];   // [S, B]
__device__ unsigned g_maxbits[BATCH];        // per-b running max (ordered-uint encoding)

// Ordered-uint encoding of float: monotonic, so atomicMax works on any sign.
__device__ __forceinline__ unsigned enc_f(float x) {
    unsigned b = __float_as_uint(x);
    return (b & 0x80000000u) ? ~b : (b | 0x80000000u);
}
__device__ __forceinline__ float dec_f(unsigned u) {
    unsigned b = (u & 0x80000000u) ? (u ^ 0x80000000u) : ~u;
    return __uint_as_float(b);
}

// ---------------------------------------------------------------------------
// Kernel 1: energy[b][j] = sum_h state[b][h] * W[j][h] + bias[j]
// No smem staging: state (64KB) is L1/L2-hot. 128 blocks x 8 warps,
// each warp computes a 4j x 4b register tile over the full H.
// Also resets g_maxbits for this graph replay (stream-ordered before scores).
// ---------------------------------------------------------------------------
__global__ void __launch_bounds__(256) energy_kernel(
    const float* __restrict__ state,   // [B, H] (= last_decoder_state[0,0])
    const float* __restrict__ W,       // [H, H]
    const float* __restrict__ bias)    // [H]
{
    if (blockIdx.x == 0 && threadIdx.x < BATCH)
        g_maxbits[threadIdx.x] = 0u;   // < enc(-inf); any real score replaces it

    const int warp = threadIdx.x >> 5;
    const int lane = threadIdx.x & 31;

    const int jgroup = warp & 1;
    const int bgroup = warp >> 1;
    const int j0 = blockIdx.x * 8 + jgroup * 4;
    const int b0 = bgroup * 4;

    const float4* w0 = (const float4*)(W + (size_t)(j0 + 0) * HID);
    const float4* w1 = (const float4*)(W + (size_t)(j0 + 1) * HID);
    const float4* w2 = (const float4*)(W + (size_t)(j0 + 2) * HID);
    const float4* w3 = (const float4*)(W + (size_t)(j0 + 3) * HID);
    const float4* s0 = (const float4*)(state + (b0 + 0) * HID);
    const float4* s1 = (const float4*)(state + (b0 + 1) * HID);
    const float4* s2 = (const float4*)(state + (b0 + 2) * HID);
    const float4* s3 = (const float4*)(state + (b0 + 3) * HID);

    float acc[4][4];
#pragma unroll
    for (int a = 0; a < 4; a++)
#pragma unroll
        for (int c = 0; c < 4; c++) acc[a][c] = 0.0f;

#pragma unroll
    for (int k = 0; k < (HID / 4) / 32; k++) {   // 8 iterations
        const int idx = lane + k * 32;
        float4 wv[4], sv[4];
        wv[0] = __ldg(w0 + idx); wv[1] = __ldg(w1 + idx);
        wv[2] = __ldg(w2 + idx); wv[3] = __ldg(w3 + idx);
        sv[0] = __ldg(s0 + idx); sv[1] = __ldg(s1 + idx);
        sv[2] = __ldg(s2 + idx); sv[3] = __ldg(s3 + idx);
#pragma unroll
        for (int jj = 0; jj < 4; jj++) {
#pragma unroll
            for (int bb = 0; bb < 4; bb++) {
                acc[jj][bb] = fmaf(wv[jj].x, sv[bb].x, acc[jj][bb]);
                acc[jj][bb] = fmaf(wv[jj].y, sv[bb].y, acc[jj][bb]);
                acc[jj][bb] = fmaf(wv[jj].z, sv[bb].z, acc[jj][bb]);
                acc[jj][bb] = fmaf(wv[jj].w, sv[bb].w, acc[jj][bb]);
            }
        }
    }

#pragma unroll
    for (int jj = 0; jj < 4; jj++)
#pragma unroll
        for (int bb = 0; bb < 4; bb++)
#pragma unroll
            for (int off = 16; off > 0; off >>= 1)
                acc[jj][bb] += __shfl_xor_sync(0xffffffffu, acc[jj][bb], off);

    if (lane < 16) {
        const int bb = lane >> 2;
        const int jj = lane & 3;
        g_energy[(b0 + bb) * HID + (j0 + jj)] = acc[jj][bb] + bias[j0 + jj];
    }
}

// ---------------------------------------------------------------------------
// Kernel 2: scores[s][b] = dot(enc[s][b][:], energy[b][:])  (H = 1024)
// One block per s, 16 warps = 16 b's. Streams the full 134 MB -> HBM-bound.
// Also folds the per-b max reduction in via atomicMax on ordered-uint bits.
// ---------------------------------------------------------------------------
__global__ void __launch_bounds__(512) scores_kernel(
    const float* __restrict__ enc)     // [S, B, H]
{
    int s    = blockIdx.x;
    int b    = threadIdx.x >> 5;
    int lane = threadIdx.x & 31;

    const float4* e  = (const float4*)(enc + ((size_t)s * BATCH + b) * HID);
    const float4* en = (const float4*)(g_energy + b * HID);

    float acc = 0.0f;
#pragma unroll
    for (int i = 0; i < HID / 4 / 32; i++) {       // 8 iterations
        float4 a = __ldg(e + lane + i * 32);
        float4 c = __ldg(en + lane + i * 32);
        acc = fmaf(a.x, c.x, acc);
        acc = fmaf(a.y, c.y, acc);
        acc = fmaf(a.z, c.z, acc);
        acc = fmaf(a.w, c.w, acc);
    }
#pragma unroll
    for (int off = 16; off > 0; off >>= 1)
        acc += __shfl_xor_sync(0xffffffffu, acc, off);
    if (lane == 0) {
        g_scores[s * BATCH + b] = acc;
        atomicMax(&g_maxbits[b], enc_f(acc));
    }
}

// ---------------------------------------------------------------------------
// Kernel 3: softmax over S for each b (max already computed by kernel 2).
// 16 blocks x 1024 threads; 2 s-values per thread, exp kept in registers
// between the sum pass and the write pass. Output layout [1,1,S,B].
// ---------------------------------------------------------------------------
__global__ void __launch_bounds__(1024) softmax_kernel(float* __restrict__ out)
{
    const int b   = blockIdx.x;
    const int tid = threadIdx.x;
    const int warp = tid >> 5, lane = tid & 31;
    __shared__ float red[32];

    const float m = dec_f(g_maxbits[b]);

    const int s0 = tid;
    const int s1 = tid + 1024;
    const float e0 = __expf(g_scores[s0 * BATCH + b] - m);
    const float e1 = __expf(g_scores[s1 * BATCH + b] - m);

    float sum = e0 + e1;
#pragma unroll
    for (int off = 16; off > 0; off >>= 1)
        sum += __shfl_xor_sync(0xffffffffu, sum, off);
    if (lane == 0) red[warp] = sum;
    __syncthreads();
    if (warp == 0) {
        float v = red[lane];
#pragma unroll
        for (int off = 16; off > 0; off >>= 1)
            v += __shfl_xor_sync(0xffffffffu, v, off);
        if (lane == 0) red[0] = v;
    }
    __syncthreads();
    const float inv = 1.0f / red[0];

    out[s0 * BATCH + b] = e0 * inv;
    out[s1 * BATCH + b] = e1 * inv;
}

// ---------------------------------------------------------------------------
extern "C" void kernel_launch(void* const* d_in, const int* in_sizes, int n_in,
                              void* d_out, int out_size)
{
    const float* enc   = (const float*)d_in[0];   // [S, B, H]
    const float* lds   = (const float*)d_in[1];   // [2, 1, B, H]
    const float* W     = (const float*)d_in[2];   // [H, H]
    const float* bias  = (const float*)d_in[3];   // [H]
    float* out = (float*)d_out;                   // [1, 1, S, B]

    // state = last_decoder_state[0, 0] -> first B*H floats
    energy_kernel<<<HID / 8, 256>>>(lds, W, bias);
    scores_kernel<<<SEQ, 512>>>(enc);
    softmax_kernel<<<BATCH, 1024>>>(out);
}